// round 16
// baseline (speedup 1.0000x reference)
#include <cuda_runtime.h>
#include <cuda_fp16.h>
#include <math.h>
#include <stdint.h>

// Problem constants
#define B_ 4
#define N_ 2048
#define C_ 512
#define H_ 8
#define DH 64
#define M_ (B_ * N_)          // 8192
#define NQKV (3 * C_)         // 1536

#define SC_LOG2E 0.18033688011112042f   // 0.125 * log2(e)
#define LOG2E    1.4426950408889634f

// Scratch (device globals; no allocation allowed)
__device__ __half g_xh[M_ * C_];
__device__ __half g_Wqkvh[NQKV * C_];
__device__ __half g_Wprojh[C_ * C_];
__device__ __half g_Qh[B_ * H_ * N_ * DH];    // pre-scaled by SC_LOG2E
__device__ __half g_Kh[B_ * H_ * N_ * DH];
__device__ __half g_Vth[B_ * H_ * DH * N_];   // V transposed: [b,h,d,n]
__device__ __half g_Oh[M_ * C_];
__device__ float g_cos[B_ * N_ * (DH / 2)];
__device__ float g_sin[B_ * N_ * (DH / 2)];

// ---------------------------------------------------------------------------
// helpers
// ---------------------------------------------------------------------------
__device__ __forceinline__ void mma16(float* c,
                                      uint32_t a0, uint32_t a1, uint32_t a2, uint32_t a3,
                                      uint32_t b0, uint32_t b1) {
    asm volatile(
        "mma.sync.aligned.m16n8k16.row.col.f32.f16.f16.f32 "
        "{%0,%1,%2,%3},{%4,%5,%6,%7},{%8,%9},{%0,%1,%2,%3};"
        : "+f"(c[0]), "+f"(c[1]), "+f"(c[2]), "+f"(c[3])
        : "r"(a0), "r"(a1), "r"(a2), "r"(a3), "r"(b0), "r"(b1));
}

__device__ __forceinline__ void ldsm4(uint32_t& r0, uint32_t& r1, uint32_t& r2, uint32_t& r3,
                                      uint32_t addr) {
    asm volatile("ldmatrix.sync.aligned.m8n8.x4.shared.b16 {%0,%1,%2,%3}, [%4];"
                 : "=r"(r0), "=r"(r1), "=r"(r2), "=r"(r3) : "r"(addr));
}

__device__ __forceinline__ void cp16(uint32_t dst, const void* src) {
    asm volatile("cp.async.cg.shared.global [%0], [%1], 16;" :: "r"(dst), "l"(src));
}
#define CP_COMMIT() asm volatile("cp.async.commit_group;")
#define CP_WAIT0()  asm volatile("cp.async.wait_group 0;")

__device__ __forceinline__ float ex2f(float x) {
    float y;
    asm("ex2.approx.ftz.f32 %0, %1;" : "=f"(y) : "f"(x));
    return y;
}

// packed half2 exp2: one MUFU op, output is a ready fp16x2 mma fragment
__device__ __forceinline__ uint32_t h2ex2(float lo, float hi) {
    __half2 t = __floats2half2_rn(lo, hi);
    uint32_t y;
    asm("ex2.approx.f16x2 %0, %1;" : "=r"(y) : "r"(*(uint32_t*)&t));
    return y;
}
__device__ __forceinline__ uint32_t h2add(uint32_t a, uint32_t b) {
    __half2 r = __hadd2(*(__half2*)&a, *(__half2*)&b);
    return *(uint32_t*)&r;
}

// ---------------------------------------------------------------------------
// Kernel: prep — fp32->fp16 of x/Wqkv/Wproj AND RoPE tables, one launch.
// ---------------------------------------------------------------------------
#define X_N4    (M_ * C_ / 4)            // 1048576
#define WQKV_N4 (NQKV * C_ / 4)          // 196608
#define WPROJ_N4 (C_ * C_ / 4)           // 65536
#define F2H_TOTAL (X_N4 + WQKV_N4 + WPROJ_N4)
#define ROPE_N (B_ * N_ * 32)
#define PREP_TOTAL (F2H_TOTAL + ROPE_N)

__global__ void prep_kernel(const float* __restrict__ x,
                            const float* __restrict__ wqkv,
                            const float* __restrict__ wproj,
                            const float* __restrict__ times) {
    int i = blockIdx.x * 256 + threadIdx.x;
    if (i < F2H_TOTAL) {
        const float* src;
        __half* dst;
        int off;
        if (i < X_N4) { src = x; dst = g_xh; off = i; }
        else if (i < X_N4 + WQKV_N4) { src = wqkv; dst = g_Wqkvh; off = i - X_N4; }
        else { src = wproj; dst = g_Wprojh; off = i - X_N4 - WQKV_N4; }
        float4 v = ((const float4*)src)[off];
        __half2* o = (__half2*)dst;
        o[2 * off]     = __floats2half2_rn(v.x, v.y);
        o[2 * off + 1] = __floats2half2_rn(v.z, v.w);
    } else if (i < PREP_TOTAL) {
        int idx = i - F2H_TOTAL;
        int fi = idx & 31;
        int bn = idx >> 5;
        float pos = rintf(times[bn] * 30.0f);
        float inv_freq = powf(10000.0f, -(float)fi / 32.0f);
        float f = pos * inv_freq;
        float s, c;
        sincosf(f, &s, &c);
        g_cos[idx] = c;
        g_sin[idx] = s;
    }
}

// ---------------------------------------------------------------------------
// Kernel 1: QKV GEMM fp16 mma (M=8192, N=1536, K=512) + RoPE + STAGED scatter.
//   (exact R14 version — best measured)
// ---------------------------------------------------------------------------
#define QKV_SMEM 40960

__global__ __launch_bounds__(256) void gemm_qkv_h() {
    extern __shared__ char dsm[];
    uint32_t base = (uint32_t)__cvta_generic_to_shared(dsm);

    int tid = threadIdx.x;
    int w = tid >> 5, lane = tid & 31;
    int lq = lane >> 2, lr = lane & 3;
    int wm = w & 1, wn = w >> 1;
    int m0 = blockIdx.y * 128;
    int n0 = blockIdx.x * 128;

    int lrow = tid >> 1;              // 0..127
    int lk = (tid & 1) * 16;          // 0 or 16
    const __half* xg = g_xh + (size_t)(m0 + lrow) * C_ + lk;
    const __half* wg = g_Wqkvh + (size_t)(n0 + lrow) * C_ + lk;

    // stages: A @ {0, 10240}; B @ {20480, 30720}
    uint32_t asb[2] = { base, base + 10240 };
    uint32_t bsb[2] = { base + 20480, base + 30720 };
    uint32_t sdst = (lrow * 40 + lk) * 2;
    uint32_t afrag = ((wm * 64 + (lane & 15)) * 40 + (lane >> 4) * 8) * 2;
    uint32_t bfrag = ((wn * 32 + (lane & 15)) * 40 + (lane >> 4) * 8) * 2;

    float c[16][4];
#pragma unroll
    for (int f = 0; f < 16; ++f)
#pragma unroll
        for (int i = 0; i < 4; ++i) c[f][i] = 0.0f;

    cp16(asb[0] + sdst, xg);      cp16(asb[0] + sdst + 16, xg + 8);
    cp16(bsb[0] + sdst, wg);      cp16(bsb[0] + sdst + 16, wg + 8);
    CP_COMMIT();
    CP_WAIT0();
    __syncthreads();

    for (int it = 0; it < 16; ++it) {
        int buf = it & 1;
        if (it < 15) {
            int k0 = (it + 1) * 32;
            cp16(asb[buf ^ 1] + sdst, xg + k0);      cp16(asb[buf ^ 1] + sdst + 16, xg + k0 + 8);
            cp16(bsb[buf ^ 1] + sdst, wg + k0);      cp16(bsb[buf ^ 1] + sdst + 16, wg + k0 + 8);
            CP_COMMIT();
        }
#pragma unroll
        for (int ks = 0; ks < 2; ++ks) {
            uint32_t a[4][4];
#pragma unroll
            for (int mf = 0; mf < 4; ++mf)
                ldsm4(a[mf][0], a[mf][1], a[mf][2], a[mf][3],
                      asb[buf] + afrag + (mf * 16 * 40 + ks * 16) * 2);
#pragma unroll
            for (int p = 0; p < 2; ++p) {
                uint32_t b0, b1, b2, b3;
                ldsm4(b0, b1, b2, b3, bsb[buf] + bfrag + (p * 16 * 40 + ks * 16) * 2);
#pragma unroll
                for (int mf = 0; mf < 4; ++mf) {
                    mma16(c[mf * 4 + 2 * p],     a[mf][0], a[mf][1], a[mf][2], a[mf][3], b0, b2);
                    mma16(c[mf * 4 + 2 * p + 1], a[mf][0], a[mf][1], a[mf][2], a[mf][3], b1, b3);
                }
            }
        }
        if (it < 15) {
            CP_WAIT0();
            __syncthreads();
        }
    }

    // --- epilogue: RoPE in-register, stage to smem, coalesced writeout ---
    __syncthreads();
    __half* S = (__half*)dsm;          // 128 x 132 halfs = 33792 B
    int s = n0 >> 9;                   // 0:q 1:k 2:v — uniform per CTA
    int bq2 = m0 >> 11;
    int nbase = m0 & 2047;

#pragma unroll
    for (int mf = 0; mf < 4; ++mf) {
#pragma unroll
        for (int half = 0; half < 2; ++half) {
            int mloc = wm * 64 + mf * 16 + lq + half * 8;
            int m = m0 + mloc;
#pragma unroll
            for (int nf = 0; nf < 4; ++nf) {
                int col = wn * 32 + nf * 8 + 2 * lr;
                float v0 = c[mf * 4 + nf][half * 2 + 0];
                float v1 = c[mf * 4 + nf][half * 2 + 1];
                __half2 hv;
                if (s == 2) {
                    hv = __floats2half2_rn(v0, v1);
                } else {
                    int d = (n0 + col) & 63;
                    int i2 = d >> 1;
                    float sc = (s == 0) ? SC_LOG2E : 1.0f;
                    float ct = g_cos[m * 32 + i2] * sc;
                    float st = g_sin[m * 32 + i2] * sc;
                    hv = __floats2half2_rn(v0 * ct - v1 * st, v0 * st + v1 * ct);
                }
                *(__half2*)&S[mloc * 132 + col] = hv;
            }
        }
    }
    __syncthreads();

    if (s < 2) {
        __half* dstb = (s == 0) ? g_Qh : g_Kh;
#pragma unroll
        for (int k2 = 0; k2 < 8; ++k2) {
            int idx = tid + k2 * 256;
            int row = idx >> 4;              // 0..127
            int cseg = (idx & 15) * 8;       // 0..120
            int cb = n0 + cseg;
            int hh = (cb >> 6) & 7;
            int dd = cb & 63;
            const uint2* sp = (const uint2*)&S[row * 132 + cseg];
            uint2 u0 = sp[0], u1 = sp[1];
            uint4 val = make_uint4(u0.x, u0.y, u1.x, u1.y);
            *(uint4*)&dstb[((size_t)((bq2 * 8 + hh) * 2048 + nbase + row)) * 64 + dd] = val;
        }
    } else {
#pragma unroll
        for (int k2 = 0; k2 < 8; ++k2) {
            int idx = tid + k2 * 256;
            int col = idx >> 4;              // 0..127
            int mseg = (idx & 15) * 8;       // 0..120
            int cb = n0 + col;
            int hh = (cb >> 6) & 7;
            int dd = cb & 63;
            __half tmp[8];
#pragma unroll
            for (int t = 0; t < 8; ++t) tmp[t] = S[(mseg + t) * 132 + col];
            *(uint4*)&g_Vth[((size_t)((bq2 * 8 + hh) * 64 + dd)) * 2048 + nbase + mseg] =
                *(uint4*)tmp;
        }
    }
}

// ---------------------------------------------------------------------------
// Kernel 2: flash attention (R9 structure), now __launch_bounds__(128, 3):
//   caps registers at 170 so 3 CTAs/SM fit -> attn wave count 1.73 -> 1.15.
// ---------------------------------------------------------------------------
__global__ __launch_bounds__(128, 3) void attn_h(const float* __restrict__ mask) {
    __shared__ __half Ks[2][64 * 72];
    __shared__ __half Vs[2][64 * 72];
    __shared__ float Ms[2][64];

    int tid = threadIdx.x;
    int w = tid >> 5, lane = tid & 31;
    int lq = lane >> 2, lr = lane & 3;
    int bh = blockIdx.y;
    int b = bh >> 3, h = bh & 7;
    int q0 = blockIdx.x * 128;

    const __half* Qg = g_Qh + ((size_t)bh * 2048 + q0) * 64;
    const __half* Kg = g_Kh + (size_t)bh * 2048 * 64;
    const __half* Vg = g_Vth + (size_t)bh * 64 * 2048;
    const float* maskb = mask + b * 2048;

    uint32_t qf[2][4][4];
#pragma unroll
    for (int blk = 0; blk < 2; ++blk) {
        int qrow = w * 32 + blk * 16 + lq;
#pragma unroll
        for (int ks = 0; ks < 4; ++ks) {
            qf[blk][ks][0] = *(const uint32_t*)(Qg + (size_t)qrow * 64 + ks * 16 + 2 * lr);
            qf[blk][ks][1] = *(const uint32_t*)(Qg + (size_t)(qrow + 8) * 64 + ks * 16 + 2 * lr);
            qf[blk][ks][2] = *(const uint32_t*)(Qg + (size_t)qrow * 64 + ks * 16 + 8 + 2 * lr);
            qf[blk][ks][3] = *(const uint32_t*)(Qg + (size_t)(qrow + 8) * 64 + ks * 16 + 8 + 2 * lr);
        }
    }

    uint32_t ksb[2] = { (uint32_t)__cvta_generic_to_shared(Ks[0]),
                        (uint32_t)__cvta_generic_to_shared(Ks[1]) };
    uint32_t vsb[2] = { (uint32_t)__cvta_generic_to_shared(Vs[0]),
                        (uint32_t)__cvta_generic_to_shared(Vs[1]) };
    uint32_t bfrag = ((lane & 15) * 72 + (lane >> 4) * 8) * 2;

    int rc[4], cc[4];
#pragma unroll
    for (int j = 0; j < 4; ++j) {
        int q = j * 128 + tid;
        rc[j] = q >> 3;
        cc[j] = (q & 7) * 8;
    }

    float co[2][8][4];
#pragma unroll
    for (int blk = 0; blk < 2; ++blk)
#pragma unroll
        for (int nf = 0; nf < 8; ++nf)
#pragma unroll
            for (int i = 0; i < 4; ++i) co[blk][nf][i] = 0.0f;
    float mi[4] = { -INFINITY, -INFINITY, -INFINITY, -INFINITY };
    float li[4] = { 0.0f, 0.0f, 0.0f, 0.0f };

    {
#pragma unroll
        for (int j = 0; j < 4; ++j) {
            cp16(ksb[0] + (rc[j] * 72 + cc[j]) * 2, Kg + (size_t)rc[j] * 64 + cc[j]);
            cp16(vsb[0] + (rc[j] * 72 + cc[j]) * 2, Vg + (size_t)rc[j] * 2048 + cc[j]);
        }
        CP_COMMIT();
        if (tid < 64) Ms[0][tid] = maskb[tid] * LOG2E;
        CP_WAIT0();
        __syncthreads();
    }

    for (int kt = 0; kt < 32; ++kt) {
        int buf = kt & 1;
        if (kt < 31) {
            int nk = kt + 1;
#pragma unroll
            for (int j = 0; j < 4; ++j) {
                cp16(ksb[buf ^ 1] + (rc[j] * 72 + cc[j]) * 2,
                     Kg + (size_t)(nk * 64 + rc[j]) * 64 + cc[j]);
                cp16(vsb[buf ^ 1] + (rc[j] * 72 + cc[j]) * 2,
                     Vg + (size_t)rc[j] * 2048 + nk * 64 + cc[j]);
            }
            CP_COMMIT();
            if (tid < 64) Ms[buf ^ 1][tid] = maskb[nk * 64 + tid] * LOG2E;
        }

        float cs[2][8][4];
#pragma unroll
        for (int blk = 0; blk < 2; ++blk)
#pragma unroll
            for (int nf = 0; nf < 8; ++nf)
#pragma unroll
                for (int i = 0; i < 4; ++i) cs[blk][nf][i] = 0.0f;

#pragma unroll
        for (int ks = 0; ks < 4; ++ks) {
#pragma unroll
            for (int p = 0; p < 4; ++p) {
                uint32_t b0, b1, b2, b3;
                ldsm4(b0, b1, b2, b3, ksb[buf] + bfrag + (p * 16 * 72 + ks * 16) * 2);
#pragma unroll
                for (int blk = 0; blk < 2; ++blk) {
                    mma16(cs[blk][2 * p],     qf[blk][ks][0], qf[blk][ks][1],
                          qf[blk][ks][2], qf[blk][ks][3], b0, b2);
                    mma16(cs[blk][2 * p + 1], qf[blk][ks][0], qf[blk][ks][1],
                          qf[blk][ks][2], qf[blk][ks][3], b1, b3);
                }
            }
        }

        float rm[4] = { -INFINITY, -INFINITY, -INFINITY, -INFINITY };
#pragma unroll
        for (int nf = 0; nf < 8; ++nf) {
            float mk0 = Ms[buf][nf * 8 + 2 * lr];
            float mk1 = Ms[buf][nf * 8 + 2 * lr + 1];
#pragma unroll
            for (int blk = 0; blk < 2; ++blk) {
                cs[blk][nf][0] += mk0;
                cs[blk][nf][1] += mk1;
                cs[blk][nf][2] += mk0;
                cs[blk][nf][3] += mk1;
                rm[2 * blk]     = fmaxf(rm[2 * blk],     fmaxf(cs[blk][nf][0], cs[blk][nf][1]));
                rm[2 * blk + 1] = fmaxf(rm[2 * blk + 1], fmaxf(cs[blk][nf][2], cs[blk][nf][3]));
            }
        }
#pragma unroll
        for (int r = 0; r < 4; ++r) {
            rm[r] = fmaxf(rm[r], __shfl_xor_sync(0xffffffffu, rm[r], 1));
            rm[r] = fmaxf(rm[r], __shfl_xor_sync(0xffffffffu, rm[r], 2));
        }

        float mn[4], corr[4];
#pragma unroll
        for (int r = 0; r < 4; ++r) {
            mn[r] = fmaxf(mi[r], rm[r]);
            corr[r] = ex2f(mi[r] - mn[r]);
        }

        uint32_t p01[2][8], p23[2][8];
#pragma unroll
        for (int blk = 0; blk < 2; ++blk)
#pragma unroll
            for (int nf = 0; nf < 8; ++nf) {
                p01[blk][nf] = h2ex2(cs[blk][nf][0] - mn[2 * blk],
                                     cs[blk][nf][1] - mn[2 * blk]);
                p23[blk][nf] = h2ex2(cs[blk][nf][2] - mn[2 * blk + 1],
                                     cs[blk][nf][3] - mn[2 * blk + 1]);
            }

        float sum[4];
#pragma unroll
        for (int blk = 0; blk < 2; ++blk) {
            uint32_t t0 = h2add(h2add(h2add(p01[blk][0], p01[blk][1]),
                                      h2add(p01[blk][2], p01[blk][3])),
                                h2add(h2add(p01[blk][4], p01[blk][5]),
                                      h2add(p01[blk][6], p01[blk][7])));
            uint32_t t1 = h2add(h2add(h2add(p23[blk][0], p23[blk][1]),
                                      h2add(p23[blk][2], p23[blk][3])),
                                h2add(h2add(p23[blk][4], p23[blk][5]),
                                      h2add(p23[blk][6], p23[blk][7])));
            float2 f0 = __half22float2(*(__half2*)&t0);
            float2 f1 = __half22float2(*(__half2*)&t1);
            sum[2 * blk]     = f0.x + f0.y;
            sum[2 * blk + 1] = f1.x + f1.y;
        }
#pragma unroll
        for (int r = 0; r < 4; ++r) {
            sum[r] += __shfl_xor_sync(0xffffffffu, sum[r], 1);
            sum[r] += __shfl_xor_sync(0xffffffffu, sum[r], 2);
            li[r] = li[r] * corr[r] + sum[r];
            mi[r] = mn[r];
        }
#pragma unroll
        for (int blk = 0; blk < 2; ++blk)
#pragma unroll
            for (int nf = 0; nf < 8; ++nf) {
                co[blk][nf][0] *= corr[2 * blk];
                co[blk][nf][1] *= corr[2 * blk];
                co[blk][nf][2] *= corr[2 * blk + 1];
                co[blk][nf][3] *= corr[2 * blk + 1];
            }

#pragma unroll
        for (int kc = 0; kc < 4; ++kc) {
#pragma unroll
            for (int p = 0; p < 4; ++p) {
                uint32_t b0, b1, b2, b3;
                ldsm4(b0, b1, b2, b3, vsb[buf] + bfrag + (p * 16 * 72 + kc * 16) * 2);
#pragma unroll
                for (int blk = 0; blk < 2; ++blk) {
                    mma16(co[blk][2 * p],     p01[blk][2 * kc], p23[blk][2 * kc],
                          p01[blk][2 * kc + 1], p23[blk][2 * kc + 1], b0, b2);
                    mma16(co[blk][2 * p + 1], p01[blk][2 * kc], p23[blk][2 * kc],
                          p01[blk][2 * kc + 1], p23[blk][2 * kc + 1], b1, b3);
                }
            }
        }

        if (kt < 31) {
            CP_WAIT0();
            __syncthreads();
        }
    }

#pragma unroll
    for (int blk = 0; blk < 2; ++blk) {
        float inv0 = 1.0f / li[2 * blk];
        float inv1 = 1.0f / li[2 * blk + 1];
        int m0g = q0 + w * 32 + blk * 16 + lq;
        int m1g = m0g + 8;
#pragma unroll
        for (int nf = 0; nf < 8; ++nf) {
            int col = h * 64 + nf * 8 + 2 * lr;
            *(__half2*)&g_Oh[((size_t)(b * 2048 + m0g)) * 512 + col] =
                __floats2half2_rn(co[blk][nf][0] * inv0, co[blk][nf][1] * inv0);
            *(__half2*)&g_Oh[((size_t)(b * 2048 + m1g)) * 512 + col] =
                __floats2half2_rn(co[blk][nf][2] * inv1, co[blk][nf][3] * inv1);
        }
    }
}

// ---------------------------------------------------------------------------
// Kernel 3: output projection fp16 mma (exact R9/R14 version)
// ---------------------------------------------------------------------------
__global__ __launch_bounds__(256) void gemm_proj_h(const float* __restrict__ bias,
                                                   float* __restrict__ out) {
    __shared__ __half As[2][128 * 40];
    __shared__ __half Bs[2][128 * 40];

    int tid = threadIdx.x;
    int w = tid >> 5, lane = tid & 31;
    int lq = lane >> 2, lr = lane & 3;
    int wm = w & 1, wn = w >> 1;
    int m0 = blockIdx.y * 128;
    int n0 = blockIdx.x * 128;

    int lrow = tid >> 1;
    int lk = (tid & 1) * 16;
    const __half* ag = g_Oh + (size_t)(m0 + lrow) * C_ + lk;
    const __half* wg = g_Wprojh + (size_t)(n0 + lrow) * C_ + lk;

    uint32_t asb[2] = { (uint32_t)__cvta_generic_to_shared(As[0]),
                        (uint32_t)__cvta_generic_to_shared(As[1]) };
    uint32_t bsb[2] = { (uint32_t)__cvta_generic_to_shared(Bs[0]),
                        (uint32_t)__cvta_generic_to_shared(Bs[1]) };
    uint32_t sdst = (lrow * 40 + lk) * 2;
    uint32_t afrag = ((wm * 64 + (lane & 15)) * 40 + (lane >> 4) * 8) * 2;
    uint32_t bfrag = ((wn * 32 + (lane & 15)) * 40 + (lane >> 4) * 8) * 2;

    float c[16][4];
#pragma unroll
    for (int f = 0; f < 16; ++f)
#pragma unroll
        for (int i = 0; i < 4; ++i) c[f][i] = 0.0f;

    cp16(asb[0] + sdst, ag);      cp16(asb[0] + sdst + 16, ag + 8);
    cp16(bsb[0] + sdst, wg);      cp16(bsb[0] + sdst + 16, wg + 8);
    CP_COMMIT();
    CP_WAIT0();
    __syncthreads();

    for (int it = 0; it < 16; ++it) {
        int buf = it & 1;
        if (it < 15) {
            int k0 = (it + 1) * 32;
            cp16(asb[buf ^ 1] + sdst, ag + k0);      cp16(asb[buf ^ 1] + sdst + 16, ag + k0 + 8);
            cp16(bsb[buf ^ 1] + sdst, wg + k0);      cp16(bsb[buf ^ 1] + sdst + 16, wg + k0 + 8);
            CP_COMMIT();
        }
#pragma unroll
        for (int ks = 0; ks < 2; ++ks) {
            uint32_t a[4][4];
#pragma unroll
            for (int mf = 0; mf < 4; ++mf)
                ldsm4(a[mf][0], a[mf][1], a[mf][2], a[mf][3],
                      asb[buf] + afrag + (mf * 16 * 40 + ks * 16) * 2);
#pragma unroll
            for (int p = 0; p < 2; ++p) {
                uint32_t b0, b1, b2, b3;
                ldsm4(b0, b1, b2, b3, bsb[buf] + bfrag + (p * 16 * 40 + ks * 16) * 2);
#pragma unroll
                for (int mf = 0; mf < 4; ++mf) {
                    mma16(c[mf * 4 + 2 * p],     a[mf][0], a[mf][1], a[mf][2], a[mf][3], b0, b2);
                    mma16(c[mf * 4 + 2 * p + 1], a[mf][0], a[mf][1], a[mf][2], a[mf][3], b1, b3);
                }
            }
        }
        if (it < 15) {
            CP_WAIT0();
            __syncthreads();
        }
    }

#pragma unroll
    for (int mf = 0; mf < 4; ++mf) {
#pragma unroll
        for (int half = 0; half < 2; ++half) {
            int m = m0 + wm * 64 + mf * 16 + lq + half * 8;
#pragma unroll
            for (int nf = 0; nf < 4; ++nf) {
                int col = n0 + wn * 32 + nf * 8 + 2 * lr;
                float v0 = c[mf * 4 + nf][half * 2 + 0] + bias[col];
                float v1 = c[mf * 4 + nf][half * 2 + 1] + bias[col + 1];
                *(float2*)&out[(size_t)m * 512 + col] = make_float2(v0, v1);
            }
        }
    }
}

// ---------------------------------------------------------------------------
extern "C" void kernel_launch(void* const* d_in, const int* in_sizes, int n_in,
                              void* d_out, int out_size) {
    const float* x     = (const float*)d_in[0];
    const float* mask  = (const float*)d_in[1];
    const float* times = (const float*)d_in[2];
    const float* Wqkv  = (const float*)d_in[3];
    const float* Wproj = (const float*)d_in[4];
    const float* bproj = (const float*)d_in[5];
    (void)in_sizes; (void)n_in; (void)out_size;   // num_cls_token == 0 (fixed input)

    prep_kernel<<<(PREP_TOTAL + 255) / 256, 256>>>(x, Wqkv, Wproj, times);

    cudaFuncSetAttribute(gemm_qkv_h, cudaFuncAttributeMaxDynamicSharedMemorySize, QKV_SMEM);
    gemm_qkv_h<<<dim3(NQKV / 128, M_ / 128), 256, QKV_SMEM>>>();

    attn_h<<<dim3(N_ / 128, B_ * H_), 128>>>(mask);

    gemm_proj_h<<<dim3(C_ / 128, M_ / 128), 256>>>(bproj, (float*)d_out);
}

// round 17
// speedup vs baseline: 1.1413x; 1.1413x over previous
#include <cuda_runtime.h>
#include <cuda_fp16.h>
#include <math.h>
#include <stdint.h>

// Problem constants
#define B_ 4
#define N_ 2048
#define C_ 512
#define H_ 8
#define DH 64
#define M_ (B_ * N_)          // 8192
#define NQKV (3 * C_)         // 1536

#define SC_LOG2E 0.18033688011112042f   // 0.125 * log2(e)
#define LOG2E    1.4426950408889634f

// Scratch (device globals; no allocation allowed)
__device__ __half g_xh[M_ * C_];
__device__ __half g_Wqkvh[NQKV * C_];
__device__ __half g_Wprojh[C_ * C_];
__device__ __half g_Qh[B_ * H_ * N_ * DH];    // pre-scaled by SC_LOG2E
__device__ __half g_Kh[B_ * H_ * N_ * DH];
__device__ __half g_Vth[B_ * H_ * DH * N_];   // V transposed: [b,h,d,n]
__device__ __half g_Oh[M_ * C_];
__device__ float g_cos[B_ * N_ * (DH / 2)];
__device__ float g_sin[B_ * N_ * (DH / 2)];

// ---------------------------------------------------------------------------
// helpers
// ---------------------------------------------------------------------------
__device__ __forceinline__ void mma16(float* c,
                                      uint32_t a0, uint32_t a1, uint32_t a2, uint32_t a3,
                                      uint32_t b0, uint32_t b1) {
    asm volatile(
        "mma.sync.aligned.m16n8k16.row.col.f32.f16.f16.f32 "
        "{%0,%1,%2,%3},{%4,%5,%6,%7},{%8,%9},{%0,%1,%2,%3};"
        : "+f"(c[0]), "+f"(c[1]), "+f"(c[2]), "+f"(c[3])
        : "r"(a0), "r"(a1), "r"(a2), "r"(a3), "r"(b0), "r"(b1));
}

__device__ __forceinline__ void ldsm4(uint32_t& r0, uint32_t& r1, uint32_t& r2, uint32_t& r3,
                                      uint32_t addr) {
    asm volatile("ldmatrix.sync.aligned.m8n8.x4.shared.b16 {%0,%1,%2,%3}, [%4];"
                 : "=r"(r0), "=r"(r1), "=r"(r2), "=r"(r3) : "r"(addr));
}

__device__ __forceinline__ void cp16(uint32_t dst, const void* src) {
    asm volatile("cp.async.cg.shared.global [%0], [%1], 16;" :: "r"(dst), "l"(src));
}
#define CP_COMMIT() asm volatile("cp.async.commit_group;")
#define CP_WAIT0()  asm volatile("cp.async.wait_group 0;")

__device__ __forceinline__ float ex2f(float x) {
    float y;
    asm("ex2.approx.ftz.f32 %0, %1;" : "=f"(y) : "f"(x));
    return y;
}

// packed half2 exp2: one MUFU op, output is a ready fp16x2 mma fragment
__device__ __forceinline__ uint32_t h2ex2(float lo, float hi) {
    __half2 t = __floats2half2_rn(lo, hi);
    uint32_t y;
    asm("ex2.approx.f16x2 %0, %1;" : "=r"(y) : "r"(*(uint32_t*)&t));
    return y;
}
__device__ __forceinline__ uint32_t h2add(uint32_t a, uint32_t b) {
    __half2 r = __hadd2(*(__half2*)&a, *(__half2*)&b);
    return *(uint32_t*)&r;
}

// ---------------------------------------------------------------------------
// Kernel: prep — fp32->fp16 of x/Wqkv/Wproj AND RoPE tables, one launch.
// ---------------------------------------------------------------------------
#define X_N4    (M_ * C_ / 4)            // 1048576
#define WQKV_N4 (NQKV * C_ / 4)          // 196608
#define WPROJ_N4 (C_ * C_ / 4)           // 65536
#define F2H_TOTAL (X_N4 + WQKV_N4 + WPROJ_N4)
#define ROPE_N (B_ * N_ * 32)
#define PREP_TOTAL (F2H_TOTAL + ROPE_N)

__global__ void prep_kernel(const float* __restrict__ x,
                            const float* __restrict__ wqkv,
                            const float* __restrict__ wproj,
                            const float* __restrict__ times) {
    int i = blockIdx.x * 256 + threadIdx.x;
    if (i < F2H_TOTAL) {
        const float* src;
        __half* dst;
        int off;
        if (i < X_N4) { src = x; dst = g_xh; off = i; }
        else if (i < X_N4 + WQKV_N4) { src = wqkv; dst = g_Wqkvh; off = i - X_N4; }
        else { src = wproj; dst = g_Wprojh; off = i - X_N4 - WQKV_N4; }
        float4 v = ((const float4*)src)[off];
        __half2* o = (__half2*)dst;
        o[2 * off]     = __floats2half2_rn(v.x, v.y);
        o[2 * off + 1] = __floats2half2_rn(v.z, v.w);
    } else if (i < PREP_TOTAL) {
        int idx = i - F2H_TOTAL;
        int fi = idx & 31;
        int bn = idx >> 5;
        float pos = rintf(times[bn] * 30.0f);
        float inv_freq = powf(10000.0f, -(float)fi / 32.0f);
        float f = pos * inv_freq;
        float s, c;
        sincosf(f, &s, &c);
        g_cos[idx] = c;
        g_sin[idx] = s;
    }
}

// ---------------------------------------------------------------------------
// Kernel 1: QKV GEMM fp16 mma (M=8192, N=1536, K=512) + RoPE + STAGED scatter.
//   (exact R14 version — best measured)
// ---------------------------------------------------------------------------
#define QKV_SMEM 40960

__global__ __launch_bounds__(256) void gemm_qkv_h() {
    extern __shared__ char dsm[];
    uint32_t base = (uint32_t)__cvta_generic_to_shared(dsm);

    int tid = threadIdx.x;
    int w = tid >> 5, lane = tid & 31;
    int lq = lane >> 2, lr = lane & 3;
    int wm = w & 1, wn = w >> 1;
    int m0 = blockIdx.y * 128;
    int n0 = blockIdx.x * 128;

    int lrow = tid >> 1;              // 0..127
    int lk = (tid & 1) * 16;          // 0 or 16
    const __half* xg = g_xh + (size_t)(m0 + lrow) * C_ + lk;
    const __half* wg = g_Wqkvh + (size_t)(n0 + lrow) * C_ + lk;

    // stages: A @ {0, 10240}; B @ {20480, 30720}
    uint32_t asb[2] = { base, base + 10240 };
    uint32_t bsb[2] = { base + 20480, base + 30720 };
    uint32_t sdst = (lrow * 40 + lk) * 2;
    uint32_t afrag = ((wm * 64 + (lane & 15)) * 40 + (lane >> 4) * 8) * 2;
    uint32_t bfrag = ((wn * 32 + (lane & 15)) * 40 + (lane >> 4) * 8) * 2;

    float c[16][4];
#pragma unroll
    for (int f = 0; f < 16; ++f)
#pragma unroll
        for (int i = 0; i < 4; ++i) c[f][i] = 0.0f;

    cp16(asb[0] + sdst, xg);      cp16(asb[0] + sdst + 16, xg + 8);
    cp16(bsb[0] + sdst, wg);      cp16(bsb[0] + sdst + 16, wg + 8);
    CP_COMMIT();
    CP_WAIT0();
    __syncthreads();

    for (int it = 0; it < 16; ++it) {
        int buf = it & 1;
        if (it < 15) {
            int k0 = (it + 1) * 32;
            cp16(asb[buf ^ 1] + sdst, xg + k0);      cp16(asb[buf ^ 1] + sdst + 16, xg + k0 + 8);
            cp16(bsb[buf ^ 1] + sdst, wg + k0);      cp16(bsb[buf ^ 1] + sdst + 16, wg + k0 + 8);
            CP_COMMIT();
        }
#pragma unroll
        for (int ks = 0; ks < 2; ++ks) {
            uint32_t a[4][4];
#pragma unroll
            for (int mf = 0; mf < 4; ++mf)
                ldsm4(a[mf][0], a[mf][1], a[mf][2], a[mf][3],
                      asb[buf] + afrag + (mf * 16 * 40 + ks * 16) * 2);
#pragma unroll
            for (int p = 0; p < 2; ++p) {
                uint32_t b0, b1, b2, b3;
                ldsm4(b0, b1, b2, b3, bsb[buf] + bfrag + (p * 16 * 40 + ks * 16) * 2);
#pragma unroll
                for (int mf = 0; mf < 4; ++mf) {
                    mma16(c[mf * 4 + 2 * p],     a[mf][0], a[mf][1], a[mf][2], a[mf][3], b0, b2);
                    mma16(c[mf * 4 + 2 * p + 1], a[mf][0], a[mf][1], a[mf][2], a[mf][3], b1, b3);
                }
            }
        }
        if (it < 15) {
            CP_WAIT0();
            __syncthreads();
        }
    }

    // --- epilogue: RoPE in-register, stage to smem, coalesced writeout ---
    __syncthreads();
    __half* S = (__half*)dsm;          // 128 x 132 halfs = 33792 B
    int s = n0 >> 9;                   // 0:q 1:k 2:v — uniform per CTA
    int bq2 = m0 >> 11;
    int nbase = m0 & 2047;

#pragma unroll
    for (int mf = 0; mf < 4; ++mf) {
#pragma unroll
        for (int half = 0; half < 2; ++half) {
            int mloc = wm * 64 + mf * 16 + lq + half * 8;
            int m = m0 + mloc;
#pragma unroll
            for (int nf = 0; nf < 4; ++nf) {
                int col = wn * 32 + nf * 8 + 2 * lr;
                float v0 = c[mf * 4 + nf][half * 2 + 0];
                float v1 = c[mf * 4 + nf][half * 2 + 1];
                __half2 hv;
                if (s == 2) {
                    hv = __floats2half2_rn(v0, v1);
                } else {
                    int d = (n0 + col) & 63;
                    int i2 = d >> 1;
                    float sc = (s == 0) ? SC_LOG2E : 1.0f;
                    float ct = g_cos[m * 32 + i2] * sc;
                    float st = g_sin[m * 32 + i2] * sc;
                    hv = __floats2half2_rn(v0 * ct - v1 * st, v0 * st + v1 * ct);
                }
                *(__half2*)&S[mloc * 132 + col] = hv;
            }
        }
    }
    __syncthreads();

    if (s < 2) {
        __half* dstb = (s == 0) ? g_Qh : g_Kh;
#pragma unroll
        for (int k2 = 0; k2 < 8; ++k2) {
            int idx = tid + k2 * 256;
            int row = idx >> 4;              // 0..127
            int cseg = (idx & 15) * 8;       // 0..120
            int cb = n0 + cseg;
            int hh = (cb >> 6) & 7;
            int dd = cb & 63;
            const uint2* sp = (const uint2*)&S[row * 132 + cseg];
            uint2 u0 = sp[0], u1 = sp[1];
            uint4 val = make_uint4(u0.x, u0.y, u1.x, u1.y);
            *(uint4*)&dstb[((size_t)((bq2 * 8 + hh) * 2048 + nbase + row)) * 64 + dd] = val;
        }
    } else {
#pragma unroll
        for (int k2 = 0; k2 < 8; ++k2) {
            int idx = tid + k2 * 256;
            int col = idx >> 4;              // 0..127
            int mseg = (idx & 15) * 8;       // 0..120
            int cb = n0 + col;
            int hh = (cb >> 6) & 7;
            int dd = cb & 63;
            __half tmp[8];
#pragma unroll
            for (int t = 0; t < 8; ++t) tmp[t] = S[(mseg + t) * 132 + col];
            *(uint4*)&g_Vth[((size_t)((bq2 * 8 + hh) * 64 + dd)) * 2048 + nbase + mseg] =
                *(uint4*)tmp;
        }
    }
}

// ---------------------------------------------------------------------------
// Kernel 2: flash attention, 64-row Q tiles: 4 warps x 16 q-rows, 128 threads.
//   ~130 regs -> 4 CTAs/SM by registers (16 warps/SM, 2x R14's TLP).
//   grid (32 q-tiles, 32 bh) = 1024 CTAs. exp2 softmax, f16x2 ex2 P.
// ---------------------------------------------------------------------------
__global__ __launch_bounds__(128) void attn_h(const float* __restrict__ mask) {
    __shared__ __half Ks[2][64 * 72];
    __shared__ __half Vs[2][64 * 72];
    __shared__ float Ms[2][64];

    int tid = threadIdx.x;
    int w = tid >> 5, lane = tid & 31;
    int lq = lane >> 2, lr = lane & 3;
    int bh = blockIdx.y;
    int b = bh >> 3, h = bh & 7;
    int q0 = blockIdx.x * 64;

    const __half* Qg = g_Qh + ((size_t)bh * 2048 + q0) * 64;
    const __half* Kg = g_Kh + (size_t)bh * 2048 * 64;
    const __half* Vg = g_Vth + (size_t)bh * 64 * 2048;
    const float* maskb = mask + b * 2048;

    // Q fragments (warp owns 16 rows)
    uint32_t qf[4][4];
    int qrow = w * 16 + lq;
#pragma unroll
    for (int ks = 0; ks < 4; ++ks) {
        qf[ks][0] = *(const uint32_t*)(Qg + (size_t)qrow * 64 + ks * 16 + 2 * lr);
        qf[ks][1] = *(const uint32_t*)(Qg + (size_t)(qrow + 8) * 64 + ks * 16 + 2 * lr);
        qf[ks][2] = *(const uint32_t*)(Qg + (size_t)qrow * 64 + ks * 16 + 8 + 2 * lr);
        qf[ks][3] = *(const uint32_t*)(Qg + (size_t)(qrow + 8) * 64 + ks * 16 + 8 + 2 * lr);
    }

    uint32_t ksb[2] = { (uint32_t)__cvta_generic_to_shared(Ks[0]),
                        (uint32_t)__cvta_generic_to_shared(Ks[1]) };
    uint32_t vsb[2] = { (uint32_t)__cvta_generic_to_shared(Vs[0]),
                        (uint32_t)__cvta_generic_to_shared(Vs[1]) };
    uint32_t bfrag = ((lane & 15) * 72 + (lane >> 4) * 8) * 2;

    int rc[4], cc[4];
#pragma unroll
    for (int j = 0; j < 4; ++j) {
        int q = j * 128 + tid;
        rc[j] = q >> 3;
        cc[j] = (q & 7) * 8;
    }

    float co[8][4];
#pragma unroll
    for (int nf = 0; nf < 8; ++nf)
#pragma unroll
        for (int i = 0; i < 4; ++i) co[nf][i] = 0.0f;
    float mi0 = -INFINITY, mi1 = -INFINITY, li0 = 0.0f, li1 = 0.0f;

    {
#pragma unroll
        for (int j = 0; j < 4; ++j) {
            cp16(ksb[0] + (rc[j] * 72 + cc[j]) * 2, Kg + (size_t)rc[j] * 64 + cc[j]);
            cp16(vsb[0] + (rc[j] * 72 + cc[j]) * 2, Vg + (size_t)rc[j] * 2048 + cc[j]);
        }
        CP_COMMIT();
        if (tid < 64) Ms[0][tid] = maskb[tid] * LOG2E;
        CP_WAIT0();
        __syncthreads();
    }

    for (int kt = 0; kt < 32; ++kt) {
        int buf = kt & 1;
        if (kt < 31) {
            int nk = kt + 1;
#pragma unroll
            for (int j = 0; j < 4; ++j) {
                cp16(ksb[buf ^ 1] + (rc[j] * 72 + cc[j]) * 2,
                     Kg + (size_t)(nk * 64 + rc[j]) * 64 + cc[j]);
                cp16(vsb[buf ^ 1] + (rc[j] * 72 + cc[j]) * 2,
                     Vg + (size_t)rc[j] * 2048 + nk * 64 + cc[j]);
            }
            CP_COMMIT();
            if (tid < 64) Ms[buf ^ 1][tid] = maskb[nk * 64 + tid] * LOG2E;
        }

        // S = Q K^T
        float cs[8][4];
#pragma unroll
        for (int nf = 0; nf < 8; ++nf)
#pragma unroll
            for (int i = 0; i < 4; ++i) cs[nf][i] = 0.0f;

#pragma unroll
        for (int ks = 0; ks < 4; ++ks) {
#pragma unroll
            for (int p = 0; p < 4; ++p) {
                uint32_t b0, b1, b2, b3;
                ldsm4(b0, b1, b2, b3, ksb[buf] + bfrag + (p * 16 * 72 + ks * 16) * 2);
                mma16(cs[2 * p],     qf[ks][0], qf[ks][1], qf[ks][2], qf[ks][3], b0, b2);
                mma16(cs[2 * p + 1], qf[ks][0], qf[ks][1], qf[ks][2], qf[ks][3], b1, b3);
            }
        }

        // mask add + online softmax (exp2 domain)
        float rm0 = -INFINITY, rm1 = -INFINITY;
#pragma unroll
        for (int nf = 0; nf < 8; ++nf) {
            float mk0 = Ms[buf][nf * 8 + 2 * lr];
            float mk1 = Ms[buf][nf * 8 + 2 * lr + 1];
            cs[nf][0] += mk0;
            cs[nf][1] += mk1;
            cs[nf][2] += mk0;
            cs[nf][3] += mk1;
            rm0 = fmaxf(rm0, fmaxf(cs[nf][0], cs[nf][1]));
            rm1 = fmaxf(rm1, fmaxf(cs[nf][2], cs[nf][3]));
        }
        rm0 = fmaxf(rm0, __shfl_xor_sync(0xffffffffu, rm0, 1));
        rm0 = fmaxf(rm0, __shfl_xor_sync(0xffffffffu, rm0, 2));
        rm1 = fmaxf(rm1, __shfl_xor_sync(0xffffffffu, rm1, 1));
        rm1 = fmaxf(rm1, __shfl_xor_sync(0xffffffffu, rm1, 2));

        float mn0 = fmaxf(mi0, rm0);
        float mn1 = fmaxf(mi1, rm1);
        float corr0 = ex2f(mi0 - mn0);
        float corr1 = ex2f(mi1 - mn1);

        uint32_t p01[8], p23[8];
#pragma unroll
        for (int nf = 0; nf < 8; ++nf) {
            p01[nf] = h2ex2(cs[nf][0] - mn0, cs[nf][1] - mn0);
            p23[nf] = h2ex2(cs[nf][2] - mn1, cs[nf][3] - mn1);
        }

        uint32_t t0 = h2add(h2add(h2add(p01[0], p01[1]), h2add(p01[2], p01[3])),
                            h2add(h2add(p01[4], p01[5]), h2add(p01[6], p01[7])));
        uint32_t t1 = h2add(h2add(h2add(p23[0], p23[1]), h2add(p23[2], p23[3])),
                            h2add(h2add(p23[4], p23[5]), h2add(p23[6], p23[7])));
        float2 f0 = __half22float2(*(__half2*)&t0);
        float2 f1 = __half22float2(*(__half2*)&t1);
        float sum0 = f0.x + f0.y;
        float sum1 = f1.x + f1.y;
        sum0 += __shfl_xor_sync(0xffffffffu, sum0, 1);
        sum0 += __shfl_xor_sync(0xffffffffu, sum0, 2);
        sum1 += __shfl_xor_sync(0xffffffffu, sum1, 1);
        sum1 += __shfl_xor_sync(0xffffffffu, sum1, 2);
        li0 = li0 * corr0 + sum0;
        li1 = li1 * corr1 + sum1;
        mi0 = mn0; mi1 = mn1;
#pragma unroll
        for (int nf = 0; nf < 8; ++nf) {
            co[nf][0] *= corr0; co[nf][1] *= corr0;
            co[nf][2] *= corr1; co[nf][3] *= corr1;
        }

        // O += P V
#pragma unroll
        for (int kc = 0; kc < 4; ++kc) {
            uint32_t pa0 = p01[2 * kc];
            uint32_t pa1 = p23[2 * kc];
            uint32_t pa2 = p01[2 * kc + 1];
            uint32_t pa3 = p23[2 * kc + 1];
#pragma unroll
            for (int p = 0; p < 4; ++p) {
                uint32_t b0, b1, b2, b3;
                ldsm4(b0, b1, b2, b3, vsb[buf] + bfrag + (p * 16 * 72 + kc * 16) * 2);
                mma16(co[2 * p],     pa0, pa1, pa2, pa3, b0, b2);
                mma16(co[2 * p + 1], pa0, pa1, pa2, pa3, b1, b3);
            }
        }

        if (kt < 31) {
            CP_WAIT0();
            __syncthreads();
        }
    }

    // normalize + write g_Oh [B,N,C] (half)
    float inv0 = 1.0f / li0;
    float inv1 = 1.0f / li1;
    int m0g = q0 + w * 16 + lq;
    int m1g = m0g + 8;
#pragma unroll
    for (int nf = 0; nf < 8; ++nf) {
        int col = h * 64 + nf * 8 + 2 * lr;
        *(__half2*)&g_Oh[((size_t)(b * 2048 + m0g)) * 512 + col] =
            __floats2half2_rn(co[nf][0] * inv0, co[nf][1] * inv0);
        *(__half2*)&g_Oh[((size_t)(b * 2048 + m1g)) * 512 + col] =
            __floats2half2_rn(co[nf][2] * inv1, co[nf][3] * inv1);
    }
}

// ---------------------------------------------------------------------------
// Kernel 3: output projection fp16 mma (exact R9/R14 version)
// ---------------------------------------------------------------------------
__global__ __launch_bounds__(256) void gemm_proj_h(const float* __restrict__ bias,
                                                   float* __restrict__ out) {
    __shared__ __half As[2][128 * 40];
    __shared__ __half Bs[2][128 * 40];

    int tid = threadIdx.x;
    int w = tid >> 5, lane = tid & 31;
    int lq = lane >> 2, lr = lane & 3;
    int wm = w & 1, wn = w >> 1;
    int m0 = blockIdx.y * 128;
    int n0 = blockIdx.x * 128;

    int lrow = tid >> 1;
    int lk = (tid & 1) * 16;
    const __half* ag = g_Oh + (size_t)(m0 + lrow) * C_ + lk;
    const __half* wg = g_Wprojh + (size_t)(n0 + lrow) * C_ + lk;

    uint32_t asb[2] = { (uint32_t)__cvta_generic_to_shared(As[0]),
                        (uint32_t)__cvta_generic_to_shared(As[1]) };
    uint32_t bsb[2] = { (uint32_t)__cvta_generic_to_shared(Bs[0]),
                        (uint32_t)__cvta_generic_to_shared(Bs[1]) };
    uint32_t sdst = (lrow * 40 + lk) * 2;
    uint32_t afrag = ((wm * 64 + (lane & 15)) * 40 + (lane >> 4) * 8) * 2;
    uint32_t bfrag = ((wn * 32 + (lane & 15)) * 40 + (lane >> 4) * 8) * 2;

    float c[16][4];
#pragma unroll
    for (int f = 0; f < 16; ++f)
#pragma unroll
        for (int i = 0; i < 4; ++i) c[f][i] = 0.0f;

    cp16(asb[0] + sdst, ag);      cp16(asb[0] + sdst + 16, ag + 8);
    cp16(bsb[0] + sdst, wg);      cp16(bsb[0] + sdst + 16, wg + 8);
    CP_COMMIT();
    CP_WAIT0();
    __syncthreads();

    for (int it = 0; it < 16; ++it) {
        int buf = it & 1;
        if (it < 15) {
            int k0 = (it + 1) * 32;
            cp16(asb[buf ^ 1] + sdst, ag + k0);      cp16(asb[buf ^ 1] + sdst + 16, ag + k0 + 8);
            cp16(bsb[buf ^ 1] + sdst, wg + k0);      cp16(bsb[buf ^ 1] + sdst + 16, wg + k0 + 8);
            CP_COMMIT();
        }
#pragma unroll
        for (int ks = 0; ks < 2; ++ks) {
            uint32_t a[4][4];
#pragma unroll
            for (int mf = 0; mf < 4; ++mf)
                ldsm4(a[mf][0], a[mf][1], a[mf][2], a[mf][3],
                      asb[buf] + afrag + (mf * 16 * 40 + ks * 16) * 2);
#pragma unroll
            for (int p = 0; p < 2; ++p) {
                uint32_t b0, b1, b2, b3;
                ldsm4(b0, b1, b2, b3, bsb[buf] + bfrag + (p * 16 * 40 + ks * 16) * 2);
#pragma unroll
                for (int mf = 0; mf < 4; ++mf) {
                    mma16(c[mf * 4 + 2 * p],     a[mf][0], a[mf][1], a[mf][2], a[mf][3], b0, b2);
                    mma16(c[mf * 4 + 2 * p + 1], a[mf][0], a[mf][1], a[mf][2], a[mf][3], b1, b3);
                }
            }
        }
        if (it < 15) {
            CP_WAIT0();
            __syncthreads();
        }
    }

#pragma unroll
    for (int mf = 0; mf < 4; ++mf) {
#pragma unroll
        for (int half = 0; half < 2; ++half) {
            int m = m0 + wm * 64 + mf * 16 + lq + half * 8;
#pragma unroll
            for (int nf = 0; nf < 4; ++nf) {
                int col = n0 + wn * 32 + nf * 8 + 2 * lr;
                float v0 = c[mf * 4 + nf][half * 2 + 0] + bias[col];
                float v1 = c[mf * 4 + nf][half * 2 + 1] + bias[col + 1];
                *(float2*)&out[(size_t)m * 512 + col] = make_float2(v0, v1);
            }
        }
    }
}

// ---------------------------------------------------------------------------
extern "C" void kernel_launch(void* const* d_in, const int* in_sizes, int n_in,
                              void* d_out, int out_size) {
    const float* x     = (const float*)d_in[0];
    const float* mask  = (const float*)d_in[1];
    const float* times = (const float*)d_in[2];
    const float* Wqkv  = (const float*)d_in[3];
    const float* Wproj = (const float*)d_in[4];
    const float* bproj = (const float*)d_in[5];
    (void)in_sizes; (void)n_in; (void)out_size;   // num_cls_token == 0 (fixed input)

    prep_kernel<<<(PREP_TOTAL + 255) / 256, 256>>>(x, Wqkv, Wproj, times);

    cudaFuncSetAttribute(gemm_qkv_h, cudaFuncAttributeMaxDynamicSharedMemorySize, QKV_SMEM);
    gemm_qkv_h<<<dim3(NQKV / 128, M_ / 128), 256, QKV_SMEM>>>();

    attn_h<<<dim3(N_ / 64, B_ * H_), 128>>>(mask);

    gemm_proj_h<<<dim3(C_ / 128, M_ / 128), 256>>>(bproj, (float*)d_out);
}